// round 1
// baseline (speedup 1.0000x reference)
#include <cuda_runtime.h>
#include <math.h>

typedef unsigned long long ull;

#define NB 32
#define NT 1000
#define ND 512
#define TT1 1001

// d_out layout: acoustic [32,1001,512] | token_num [32] | alphas_t [32,1001] | cif_peak [32,1001] | token_num2 [32]
#define N_AC   (NB*TT1*ND)        /* 16,400,384 */
#define OFF_TN (N_AC)
#define OFF_AT (OFF_TN + NB)
#define OFF_CP (OFF_AT + NB*TT1)
#define OFF_TN2 (OFF_CP + NB*TT1)

// ---------------- scratch (static device globals; no runtime allocs) ----------------
__device__ float g_y[NB*NT*ND];      // relu(conv) output, 65.5 MB
__device__ float g_Wt[3*ND*ND];      // conv weights re-laid as [k][i][o]
__device__ float g_v[5*ND];          // folded ConvTranspose*w2: v[j][i]
__device__ float g_c2;               // up_b . w2 + b2
__device__ float g_a2sum[NB*NT];     // per-frame sum_j alphas2
__device__ float g_coeff[NB*TT1];    // CIF per-step coefficient (cur)
__device__ int   g_firepos[NB*TT1];
__device__ int   g_ntok[NB];

__device__ __forceinline__ void ffma2(ull &d, ull a, ull b) {
    asm("fma.rn.f32x2 %0, %1, %2, %0;" : "+l"(d) : "l"(a), "l"(b));
}

__device__ __forceinline__ float sigmoidf_acc(float x) {
    // numerically-stable form matching jax.nn.sigmoid
    if (x >= 0.f) { float z = expf(-x); return 1.f / (1.f + z); }
    float z = expf(x); return z / (1.f + z);
}

// ---------------- prep kernels ----------------
__global__ void k_prep_wt(const float* __restrict__ cw) {
    int idx = blockIdx.x * blockDim.x + threadIdx.x;   // over 3*512*512
    if (idx < 3*ND*ND) {
        int o = idx & 511;
        int i = (idx >> 9) & 511;
        int k = idx >> 18;
        g_Wt[idx] = cw[(o*ND + i)*3 + k];
    }
}

__global__ void k_prep_v(const float* __restrict__ uw, const float* __restrict__ w2) {
    int i = blockIdx.x;                 // 512 blocks
    int j = threadIdx.x >> 5;           // 5 warps
    int lane = threadIdx.x & 31;
    float s = 0.f;
    for (int o = lane; o < ND; o += 32)
        s += uw[((size_t)i*ND + o)*5 + j] * w2[o];
    #pragma unroll
    for (int o = 16; o > 0; o >>= 1) s += __shfl_xor_sync(0xffffffffu, s, o);
    if (lane == 0) g_v[j*ND + i] = s;
}

__global__ void k_prep_c2(const float* __restrict__ ub, const float* __restrict__ w2,
                          const float* __restrict__ b2) {
    int lane = threadIdx.x;
    float s = 0.f;
    for (int o = lane; o < ND; o += 32) s += ub[o] * w2[o];
    #pragma unroll
    for (int o = 16; o > 0; o >>= 1) s += __shfl_xor_sync(0xffffffffu, s, o);
    if (lane == 0) g_c2 = s + b2[0];
}

// ---------------- K1: fused conv GEMM (fp32, FFMA2 inner loop) ----------------
// C[t,o] = relu( sum_{k,i} enc[b, t+k-1, i] * Wt[k][i][o] + conv_b[o] )
// tiles: BM=128 (t), BN=128 (o), BK=16 (i), k=0..2 folded; 256 threads, 8x8 thread tile.
__global__ void __launch_bounds__(256) k_conv_gemm(const float* __restrict__ enc,
                                                   const float* __restrict__ cb) {
    const int b  = blockIdx.z;
    const int t0 = blockIdx.x * 128;
    const int o0 = blockIdx.y * 128;
    const int tid = threadIdx.x;
    const int tx = tid & 15;     // o direction
    const int ty = tid >> 4;     // t direction

    __shared__ __align__(16) float2 As2[16][132];     // [i][row], row r -> t = t0-1+r, value duplicated (v,v)
    __shared__ __align__(16) float  Bs[3][16][128];   // [k][i][o]

    ull acc[8][4];
    #pragma unroll
    for (int m = 0; m < 8; ++m)
        #pragma unroll
        for (int n = 0; n < 4; ++n) acc[m][n] = 0ull;

    for (int i0 = 0; i0 < ND; i0 += 16) {
        // ---- load A tile (130 rows x 16 cols), duplicated pairs, zero-padded halo ----
        #pragma unroll
        for (int p = 0; p < 3; ++p) {
            int idx = tid + p*256;
            if (idx < 520) {
                int r  = idx >> 2;
                int c4 = idx & 3;
                int t  = t0 - 1 + r;
                float4 val = make_float4(0.f,0.f,0.f,0.f);
                if (t >= 0 && t < NT)
                    val = *(const float4*)(enc + ((size_t)b*NT + t)*ND + i0 + c4*4);
                As2[c4*4+0][r] = make_float2(val.x, val.x);
                As2[c4*4+1][r] = make_float2(val.y, val.y);
                As2[c4*4+2][r] = make_float2(val.z, val.z);
                As2[c4*4+3][r] = make_float2(val.w, val.w);
            }
        }
        // ---- load B tile: Wt[k][i0+ii][o0..o0+127] ----
        #pragma unroll
        for (int p = 0; p < 6; ++p) {
            int idx = tid + p*256;                 // < 1536 float4s
            int kk = idx >> 9;
            int ii = (idx >> 5) & 15;
            int c4 = idx & 31;
            *(float4*)&Bs[kk][ii][c4*4] =
                *(const float4*)(g_Wt + ((size_t)kk*ND + i0 + ii)*ND + o0 + c4*4);
        }
        __syncthreads();

        #pragma unroll
        for (int ii = 0; ii < 16; ++ii) {
            ull a[10];
            const ulonglong2* ap = (const ulonglong2*)&As2[ii][ty*8];
            ulonglong2 q;
            q = ap[0]; a[0] = q.x; a[1] = q.y;
            q = ap[1]; a[2] = q.x; a[3] = q.y;
            q = ap[2]; a[4] = q.x; a[5] = q.y;
            q = ap[3]; a[6] = q.x; a[7] = q.y;
            q = ap[4]; a[8] = q.x; a[9] = q.y;
            #pragma unroll
            for (int k = 0; k < 3; ++k) {
                const ulonglong2* bp = (const ulonglong2*)&Bs[k][ii][tx*8];
                ulonglong2 b01 = bp[0];
                ulonglong2 b23 = bp[1];
                #pragma unroll
                for (int m = 0; m < 8; ++m) {
                    ffma2(acc[m][0], a[m+k], b01.x);
                    ffma2(acc[m][1], a[m+k], b01.y);
                    ffma2(acc[m][2], a[m+k], b23.x);
                    ffma2(acc[m][3], a[m+k], b23.y);
                }
            }
        }
        __syncthreads();
    }

    // ---- epilogue: +bias, relu, store to g_y ----
    float bias[8];
    #pragma unroll
    for (int j = 0; j < 8; ++j) bias[j] = cb[o0 + tx*8 + j];
    #pragma unroll
    for (int m = 0; m < 8; ++m) {
        int t = t0 + ty*8 + m;
        if (t < NT) {
            float outv[8];
            #pragma unroll
            for (int n = 0; n < 4; ++n) {
                float lo = __uint_as_float((unsigned)(acc[m][n] & 0xffffffffull));
                float hi = __uint_as_float((unsigned)(acc[m][n] >> 32));
                outv[2*n]   = fmaxf(lo + bias[2*n],   0.f);
                outv[2*n+1] = fmaxf(hi + bias[2*n+1], 0.f);
            }
            float4* yp = (float4*)(g_y + ((size_t)b*NT + t)*ND + o0 + tx*8);
            yp[0] = make_float4(outv[0], outv[1], outv[2], outv[3]);
            yp[1] = make_float4(outv[4], outv[5], outv[6], outv[7]);
        }
    }
}

// ---------------- K2: projections -> alphas_t[t<T], a2sum ----------------
__global__ void __launch_bounds__(256) k_proj(const float* __restrict__ mask,
        const float* __restrict__ w1, const float* __restrict__ b1,
        float* __restrict__ out_at) {
    int warp = threadIdx.x >> 5, lane = threadIdx.x & 31;
    int m = blockIdx.x * 8 + warp;
    if (m >= NB*NT) return;
    int b = m / NT, t = m - b*NT;
    const float4* yr  = (const float4*)(g_y + (size_t)m*ND);
    const float4* w1r = (const float4*)w1;
    float s[6] = {0.f,0.f,0.f,0.f,0.f,0.f};
    #pragma unroll
    for (int r = 0; r < 4; ++r) {
        int i4 = lane + 32*r;
        float4 h = yr[i4];
        float4 w = w1r[i4];
        s[0] += h.x*w.x + h.y*w.y + h.z*w.z + h.w*w.w;
        #pragma unroll
        for (int j = 0; j < 5; ++j) {
            float4 vv = *(const float4*)(g_v + j*ND + i4*4);
            s[1+j] += h.x*vv.x + h.y*vv.y + h.z*vv.z + h.w*vv.w;
        }
    }
    #pragma unroll
    for (int q = 0; q < 6; ++q)
        #pragma unroll
        for (int o = 16; o > 0; o >>= 1)
            s[q] += __shfl_xor_sync(0xffffffffu, s[q], o);
    if (lane == 0) {
        float mv = mask[b*NT + t];
        float alpha = fmaxf(sigmoidf_acc(s[0] + b1[0]), 0.f) * mv;
        float m2 = (t == 0) ? 1.f : mask[b*NT + t - 1];
        out_at[b*TT1 + t] = alpha + (m2 - mv) * 0.45f;   // + tail_add (0 in interior for all-ones mask)
        float c2 = g_c2;
        float s2 = 0.f;
        #pragma unroll
        for (int j = 0; j < 5; ++j) s2 += fmaxf(sigmoidf_acc(s[1+j] + c2), 0.f);
        g_a2sum[m] = s2 * mv;
    }
}

// ---------------- K3: scalar CIF scan per batch (1 warp/b) ----------------
__global__ void k_scan(const float* __restrict__ mask, float* __restrict__ out) {
    int b = blockIdx.x, lane = threadIdx.x;   // blockDim = 32
    float* out_at = out + OFF_AT;
    float* out_cp = out + OFF_CP;

    // token_num2 (deterministic strided + tree, double accumulate)
    double s2 = 0.0;
    for (int t = lane; t < NT; t += 32) s2 += (double)g_a2sum[b*NT + t];
    #pragma unroll
    for (int o = 16; o > 0; o >>= 1) s2 += __shfl_xor_sync(0xffffffffu, s2, o);
    if (lane == 0) out[OFF_TN2 + b] = (float)s2;

    float tailv = mask[b*NT + NT - 1] * 0.45f;
    if (lane == 0) out_at[b*TT1 + NT] = tailv;

    float integ = 0.f; double asum = 0.0; int ntok = 0;
    for (int c = 0; c < TT1; c += 32) {
        int t = c + lane;
        float av = 0.f;
        if (t < NT) av = out_at[b*TT1 + t];
        else if (t == NT) av = tailv;
        float my_peak = 0.f, my_coeff = 0.f;
        int lim = TT1 - c; if (lim > 32) lim = 32;
        for (int s = 0; s < lim; ++s) {
            float alpha = __shfl_sync(0xffffffffu, av, s);
            asum += (double)alpha;
            float dist = 1.f - integ;
            integ += alpha;
            float fires = integ;
            float cur = alpha;
            if (fires >= 1.f) {
                integ -= 1.f;
                cur = dist;
                if (lane == 0) g_firepos[b*TT1 + ntok] = c + s;
                ntok++;
            }
            if (lane == s) { my_peak = fires; my_coeff = cur; }
        }
        if (t < TT1) { out_cp[b*TT1 + t] = my_peak; g_coeff[b*TT1 + t] = my_coeff; }
    }
    if (lane == 0) { out[OFF_TN + b] = floorf((float)asum); g_ntok[b] = ntok; }
}

// ---------------- K4: parallel token gather-sum ----------------
__global__ void __launch_bounds__(128) k_gather(const float* __restrict__ enc,
                                                float* __restrict__ out) {
    int b = blockIdx.y, n = blockIdx.x, tid = threadIdx.x;
    const float* at = out + OFF_AT;
    float4 acc = make_float4(0.f,0.f,0.f,0.f);
    if (n < g_ntok[b]) {
        int te = g_firepos[b*TT1 + n];
        int tstart = 0;
        if (n > 0) {
            int tp = g_firepos[b*TT1 + n - 1];
            float lw = at[b*TT1 + tp] - g_coeff[b*TT1 + tp];  // alpha - dist leftover
            if (tp < NT) {
                float4 h = *(const float4*)(enc + ((size_t)b*NT + tp)*ND + tid*4);
                acc.x = lw*h.x; acc.y = lw*h.y; acc.z = lw*h.z; acc.w = lw*h.w;
            }
            tstart = tp + 1;
        }
        for (int t = tstart; t <= te; ++t) {
            if (t >= NT) break;  // hidden row T is zeros
            float cf = g_coeff[b*TT1 + t];
            float4 h = *(const float4*)(enc + ((size_t)b*NT + t)*ND + tid*4);
            acc.x = fmaf(cf, h.x, acc.x);
            acc.y = fmaf(cf, h.y, acc.y);
            acc.z = fmaf(cf, h.z, acc.z);
            acc.w = fmaf(cf, h.w, acc.w);
        }
    }
    *(float4*)(out + ((size_t)(b*TT1 + n))*ND + tid*4) = acc;
}

// ---------------- launch ----------------
extern "C" void kernel_launch(void* const* d_in, const int* in_sizes, int n_in,
                              void* d_out, int out_size) {
    (void)in_sizes; (void)n_in; (void)out_size;
    const float* enc  = (const float*)d_in[0];
    const float* mask = (const float*)d_in[1];
    const float* cw   = (const float*)d_in[2];
    const float* cb   = (const float*)d_in[3];
    const float* uw   = (const float*)d_in[4];
    const float* ub   = (const float*)d_in[5];
    const float* w1   = (const float*)d_in[6];
    const float* b1   = (const float*)d_in[7];
    const float* w2   = (const float*)d_in[8];
    const float* b2   = (const float*)d_in[9];
    float* out = (float*)d_out;

    k_prep_wt<<<(3*ND*ND + 255)/256, 256>>>(cw);
    k_prep_v<<<ND, 160>>>(uw, w2);
    k_prep_c2<<<1, 32>>>(ub, w2, b2);

    dim3 g1(8, 4, NB);               // t-tiles x o-tiles x batch
    k_conv_gemm<<<g1, 256>>>(enc, cb);

    k_proj<<<(NB*NT)/8, 256>>>(mask, w1, b1, out + OFF_AT);
    k_scan<<<NB, 32>>>(mask, out);

    dim3 g4(TT1, NB);
    k_gather<<<g4, 128>>>(enc, out);
}